// round 8
// baseline (speedup 1.0000x reference)
#include <cuda_runtime.h>
#include <cuda_fp16.h>

// PPISP pipeline. Round 8: cut instructions AND L1 wavefronts together.
//  - fp32 tables in smem (kills ~20 F2F cvts/point; only m20/m21 stay half)
//  - frame record = 2 x float4 (32B): {m00,m01,m02,m10} {m11,m12,m22,h2(m20,m21)}
//  - camera tables fully fp32: cpA={v0,v1,p2,p3} cpB={p4,d,a,hc} hb quad
//  - warp-staged float4 output stores (9 -> 3 wavefronts per warp)
//  1 point/thread, launch_bounds(256,6), ~35.5KB smem/block.

#define MAX_F 4096

__device__ float4 g_f0[MAX_F];
__device__ float4 g_f1[MAX_F];
__device__ __align__(128) float4 g_cpA[12];   // [j*4+c]
__device__ __align__(128) float4 g_cpB[12];   // [j*4+c]
__device__ __align__(64)  float4 g_hb[4];     // per camera {hb0,hb1,hb2,_}

__device__ __forceinline__ unsigned int f2h2(float a, float b) {
    __half2 h = __floats2half2_rn(a, b);
    return *reinterpret_cast<unsigned int*>(&h);
}
__device__ __forceinline__ float2 h22f2(unsigned int u) {
    __half2 h = *reinterpret_cast<__half2*>(&u);
    return __half22float2(h);
}

__global__ void ppisp_precompute(const float* __restrict__ expo,
                                 const float* __restrict__ vig,
                                 const float* __restrict__ colp,
                                 const float* __restrict__ crf,
                                 int F, int C)
{
    int t = blockIdx.x * blockDim.x + threadIdx.x;
    if (t < F) {
        float e  = exp2f(expo[t]);
        const float* cp = colp + t * 8;
        float s0 = e * expf(cp[0]);
        float s1 = e;
        float s2 = e * expf(cp[1]);
        float o0 = cp[2], o1 = cp[3], o2 = cp[4];
        float o3 = cp[5], o4 = cp[6], o5 = cp[7];
        float m00 = (1.0f - o0 - o1) * s0, m01 = o0 * s1, m02 = o1 * s2;
        float m10 = o2 * s0, m11 = (1.0f - o2 - o3) * s1, m12 = o3 * s2;
        float m20 = o4 * s0, m21 = o5 * s1, m22 = (1.0f - o4 - o5) * s2;
        g_f0[t] = make_float4(m00, m01, m02, m10);
        float4 f1;
        f1.x = m11; f1.y = m12; f1.z = m22;
        f1.w = __uint_as_float(f2h2(m20, m21));
        g_f1[t] = f1;
    }
    if (blockIdx.x == 0 && (int)threadIdx.x < C * 3 && (int)threadIdx.x < 12) {
        int c = threadIdx.x / 3;
        int j = threadIdx.x % 3;
        const float* vp = vig + c * 15 + j * 5;
        const float* kp = crf + c * 12 + j * 4;
        float a  = log1pf(expf(kp[0])) + 0.3f;   // accurate softplus (once)
        float cc = log1pf(expf(kp[2])) + 0.1f;
        float d  = kp[3];
        g_cpA[j * 4 + c] = make_float4(vp[0], vp[1], vp[2], vp[3]);
        g_cpB[j * 4 + c] = make_float4(vp[4], d, a, 0.5f / cc);
    }
    if (blockIdx.x == 0 && (int)threadIdx.x < C && (int)threadIdx.x < 4) {
        int c = threadIdx.x;
        const float* kp = crf + c * 12;
        float4 H;
        H.x = 0.5f * (log1pf(expf(kp[1]))  + 0.3f);
        H.y = 0.5f * (log1pf(expf(kp[5]))  + 0.3f);
        H.z = 0.5f * (log1pf(expf(kp[9]))  + 0.3f);
        H.w = 0.0f;
        g_hb[c] = H;
    }
}

__device__ __forceinline__ float fast_lg2(float x) {
    float y; asm("lg2.approx.f32 %0, %1;" : "=f"(y) : "f"(x)); return y;
}
__device__ __forceinline__ float fast_ex2(float x) {
    float y; asm("ex2.approx.f32 %0, %1;" : "=f"(y) : "f"(x)); return y;
}
__device__ __forceinline__ float fast_tanh(float x) {
    float y; asm("tanh.approx.f32 %0, %1;" : "=f"(y) : "f"(x)); return y;
}

__global__ void __launch_bounds__(256, 6)
ppisp_main(const float* __restrict__ rgb,
           const float* __restrict__ coords,
           const int*   __restrict__ cam,
           const int*   __restrict__ frm,
           const int*   __restrict__ pW,
           const int*   __restrict__ pH,
           float* __restrict__ out,
           int B, int F)
{
    extern __shared__ float4 smbase[];
    float4* s_f0  = smbase;                 // [F]
    float4* s_f1  = s_f0 + F;               // [F]
    float4* s_cpA = s_f1 + F;               // [12]
    float4* s_cpB = s_cpA + 12;             // [12]
    float4* s_hb  = s_cpB + 12;             // [4]
    float*  s_out = (float*)(s_hb + 4);     // [8 warps][96]

    for (int i = threadIdx.x; i < F; i += blockDim.x) {
        s_f0[i] = g_f0[i];
        s_f1[i] = g_f1[i];
    }
    if (threadIdx.x < 12) {
        s_cpA[threadIdx.x] = g_cpA[threadIdx.x];
        s_cpB[threadIdx.x] = g_cpB[threadIdx.x];
    }
    if (threadIdx.x < 4) s_hb[threadIdx.x] = g_hb[threadIdx.x];
    __syncthreads();

    float invW2 = 2.0f / (float)__ldg(pW);
    float invH2 = 2.0f / (float)__ldg(pH);

    int lane = threadIdx.x & 31;
    float* so = s_out + (threadIdx.x >> 5) * 96;

    for (int i = blockIdx.x * blockDim.x + threadIdx.x; ; ) {
        bool active = (i < B);
        // whole-warp termination check (i is lane-consecutive)
        if (__all_sync(0xFFFFFFFFu, !active)) break;

        float o0 = 0.f, o1 = 0.f, o2 = 0.f;
        if (active) {
            float r  = rgb[3 * i + 0];
            float g  = rgb[3 * i + 1];
            float b  = rgb[3 * i + 2];
            float px = coords[2 * i + 0];
            float py = coords[2 * i + 1];
            int   c  = cam[i];
            int   f  = frm[i];

            float u = fmaf(px, invW2, -1.0f);
            float v = fmaf(py, invH2, -1.0f);

            float rgbv[3] = {r, g, b};
            float t[3], aj[3], dj[3], hcj[3];
#pragma unroll
            for (int j = 0; j < 3; j++) {
                float4 A = s_cpA[j * 4 + c];
                float4 Bq = s_cpB[j * 4 + c];
                float du = u - A.x;
                float dv = v - A.y;
                float r2 = fmaf(du, du, dv * dv);
                float gn = fmaf(r2, fmaf(r2, fmaf(r2, Bq.x, A.w), A.z), 1.0f);
                t[j]   = rgbv[j] * gn;
                dj[j]  = Bq.y;
                aj[j]  = Bq.z;
                hcj[j] = Bq.w;
            }

            float4 f0 = s_f0[f];
            float4 f1 = s_f1[f];
            float2 m2021 = h22f2(__float_as_uint(f1.w));

            float y0 = fmaf(f0.x,    t[0], fmaf(f0.y,    t[1], f0.z    * t[2]));
            float y1 = fmaf(f0.w,    t[0], fmaf(f1.x,    t[1], f1.y    * t[2]));
            float y2 = fmaf(m2021.x, t[0], fmaf(m2021.y, t[1], f1.z    * t[2]));
            float yv[3] = {y0, y1, y2};

            float4 HB = s_hb[c];
            float hb[3] = {HB.x, HB.y, HB.z};
            float ov[3];
#pragma unroll
            for (int j = 0; j < 3; j++) {
                float xp  = fast_ex2(aj[j] * fast_lg2(fmaxf(yv[j], 1e-6f)));
                float arg = (xp - dj[j]) * hcj[j];
                ov[j] = fmaf(hb[j], fast_tanh(arg), hb[j]);
            }
            o0 = ov[0]; o1 = ov[1]; o2 = ov[2];
        }

        if (__all_sync(0xFFFFFFFFu, active)) {
            // full warp: stage 96 floats, store as 24 contiguous float4
            so[3 * lane + 0] = o0;
            so[3 * lane + 1] = o1;
            so[3 * lane + 2] = o2;
            __syncwarp();
            if (lane < 24) {
                int wbase = i - lane;                 // first point of warp
                float4 vv = ((const float4*)so)[lane];
                ((float4*)out)[(wbase * 3) / 4 + lane] = vv;
            }
            __syncwarp();
        } else if (active) {
            out[3 * i + 0] = o0;
            out[3 * i + 1] = o1;
            out[3 * i + 2] = o2;
        }

        i += gridDim.x * blockDim.x;
    }
}

extern "C" void kernel_launch(void* const* d_in, const int* in_sizes, int n_in,
                              void* d_out, int out_size) {
    const float* expo   = (const float*)d_in[0];
    const float* vig    = (const float*)d_in[1];
    const float* colp   = (const float*)d_in[2];
    const float* crf    = (const float*)d_in[3];
    const float* rgb    = (const float*)d_in[4];
    const float* coords = (const float*)d_in[5];
    const int*   cam    = (const int*)d_in[6];
    const int*   frm    = (const int*)d_in[7];
    const int*   pW     = (const int*)d_in[8];
    const int*   pH     = (const int*)d_in[9];
    float* out = (float*)d_out;

    int F = in_sizes[0];
    int C = in_sizes[1] / 15;
    int B = in_sizes[6];
    if (F > MAX_F) F = MAX_F;   // table capacity guard (problem uses F=1000)

    // s_f0[F] + s_f1[F] + cpA[12] + cpB[12] + hb[4] + out-stage 8*96 floats
    size_t shmem = (size_t)F * 32 + 28 * 16 + 8 * 96 * 4;

    {
        int pthreads = 256;
        int pwork = (F > C * 3) ? F : C * 3;
        int pblocks = (pwork + pthreads - 1) / pthreads;
        ppisp_precompute<<<pblocks, pthreads>>>(expo, vig, colp, crf, F, C);
    }

    static bool attr_done = false;
    if (!attr_done) {
        cudaFuncSetAttribute(ppisp_main,
                             cudaFuncAttributeMaxDynamicSharedMemorySize,
                             (int)shmem > 49152 ? (int)shmem : 49152);
        attr_done = true;
    }

    int blocks = (B + 255) / 256;
    int maxb = 148 * 6;
    if (blocks > maxb) blocks = maxb;
    ppisp_main<<<blocks, 256, shmem>>>(rgb, coords, cam, frm, pW, pH,
                                       out, B, F);
}

// round 9
// speedup vs baseline: 1.0818x; 1.0818x over previous
#include <cuda_runtime.h>
#include <cuda_fp16.h>

// PPISP pipeline. Round 9 = Round 7 (best) + fp32 camera tables (the one
// verified-good piece of round 8). 1 point/thread, <=32 regs, 8 blocks/SM.
//
// Tables (K1):
//   frame (24B, mixed precision, 2 LDS per gather):
//     g_q[f] = float4 {m00, m11, m22, bits(h2(m01,m02))}
//     g_u[f] = uint2  {bits(h2(m10,m12)), bits(h2(m20,m21))}
//   camera (fp32, broadcast LDS, zero unpacks):
//     g_cpA[j*4+c] = {v0, v1, p2, p3}
//     g_cpB[j*4+c] = {p4, d, a, hc}      hc = 0.5/c_crf
//     g_hb[c]      = {hb0, hb1, hb2, 0}  hb = 0.5*b
//   out = hb + hb*tanh((xp-d)*hc),  xp = ex2(a*lg2(max(y,1e-6)))

#define MAX_F 4096

__device__ float4 g_q[MAX_F];
__device__ uint2  g_u[MAX_F];
__device__ __align__(128) float4 g_cpA[12];
__device__ __align__(128) float4 g_cpB[12];
__device__ __align__(64)  float4 g_hb[4];

__device__ __forceinline__ unsigned int f2h2(float a, float b) {
    __half2 h = __floats2half2_rn(a, b);
    return *reinterpret_cast<unsigned int*>(&h);
}
__device__ __forceinline__ float2 h22f2(unsigned int u) {
    __half2 h = *reinterpret_cast<__half2*>(&u);
    return __half22float2(h);
}

__global__ void ppisp_precompute(const float* __restrict__ expo,
                                 const float* __restrict__ vig,
                                 const float* __restrict__ colp,
                                 const float* __restrict__ crf,
                                 int F, int C)
{
    int t = blockIdx.x * blockDim.x + threadIdx.x;
    if (t < F) {
        float e  = exp2f(expo[t]);
        const float* cp = colp + t * 8;
        float s0 = e * expf(cp[0]);
        float s1 = e;
        float s2 = e * expf(cp[1]);
        float o0 = cp[2], o1 = cp[3], o2 = cp[4];
        float o3 = cp[5], o4 = cp[6], o5 = cp[7];
        float m00 = (1.0f - o0 - o1) * s0, m01 = o0 * s1, m02 = o1 * s2;
        float m10 = o2 * s0, m11 = (1.0f - o2 - o3) * s1, m12 = o3 * s2;
        float m20 = o4 * s0, m21 = o5 * s1, m22 = (1.0f - o4 - o5) * s2;
        float4 q;
        q.x = m00; q.y = m11; q.z = m22;
        q.w = __uint_as_float(f2h2(m01, m02));
        g_q[t] = q;
        g_u[t] = make_uint2(f2h2(m10, m12), f2h2(m20, m21));
    }
    if (blockIdx.x == 0 && (int)threadIdx.x < C * 3 && (int)threadIdx.x < 12) {
        int c = threadIdx.x / 3;
        int j = threadIdx.x % 3;
        const float* vp = vig + c * 15 + j * 5;
        const float* kp = crf + c * 12 + j * 4;
        float a  = log1pf(expf(kp[0])) + 0.3f;   // accurate softplus (once)
        float cc = log1pf(expf(kp[2])) + 0.1f;
        float d  = kp[3];
        g_cpA[j * 4 + c] = make_float4(vp[0], vp[1], vp[2], vp[3]);
        g_cpB[j * 4 + c] = make_float4(vp[4], d, a, 0.5f / cc);
    }
    if (blockIdx.x == 0 && (int)threadIdx.x < C && (int)threadIdx.x < 4) {
        int c = threadIdx.x;
        const float* kp = crf + c * 12;
        float4 H;
        H.x = 0.5f * (log1pf(expf(kp[1])) + 0.3f);
        H.y = 0.5f * (log1pf(expf(kp[5])) + 0.3f);
        H.z = 0.5f * (log1pf(expf(kp[9])) + 0.3f);
        H.w = 0.0f;
        g_hb[c] = H;
    }
}

__device__ __forceinline__ float fast_lg2(float x) {
    float y; asm("lg2.approx.f32 %0, %1;" : "=f"(y) : "f"(x)); return y;
}
__device__ __forceinline__ float fast_ex2(float x) {
    float y; asm("ex2.approx.f32 %0, %1;" : "=f"(y) : "f"(x)); return y;
}
__device__ __forceinline__ float fast_tanh(float x) {
    float y; asm("tanh.approx.f32 %0, %1;" : "=f"(y) : "f"(x)); return y;
}

__global__ void __launch_bounds__(256, 8)
ppisp_main(const float* __restrict__ rgb,
           const float* __restrict__ coords,
           const int*   __restrict__ cam,
           const int*   __restrict__ frm,
           const int*   __restrict__ pW,
           const int*   __restrict__ pH,
           float* __restrict__ out,
           int B, int F)
{
    extern __shared__ float4 smbase[];
    float4* s_q   = smbase;                 // [F] 16B
    float4* s_cpA = s_q + F;                // [12]
    float4* s_cpB = s_cpA + 12;             // [12]
    float4* s_hb  = s_cpB + 12;             // [4]
    uint2*  s_u   = (uint2*)(s_hb + 4);     // [F] 8B

    for (int i = threadIdx.x; i < F; i += blockDim.x) {
        s_q[i] = g_q[i];
        s_u[i] = g_u[i];
    }
    if (threadIdx.x < 12) {
        s_cpA[threadIdx.x] = g_cpA[threadIdx.x];
        s_cpB[threadIdx.x] = g_cpB[threadIdx.x];
    }
    if (threadIdx.x < 4) s_hb[threadIdx.x] = g_hb[threadIdx.x];
    __syncthreads();

    float invW2 = 2.0f / (float)__ldg(pW);
    float invH2 = 2.0f / (float)__ldg(pH);

    for (int i = blockIdx.x * blockDim.x + threadIdx.x; i < B;
         i += gridDim.x * blockDim.x) {
        float r  = rgb[3 * i + 0];
        float g  = rgb[3 * i + 1];
        float b  = rgb[3 * i + 2];
        float px = coords[2 * i + 0];
        float py = coords[2 * i + 1];
        int   c  = cam[i];
        int   f  = frm[i];

        float u = fmaf(px, invW2, -1.0f);
        float v = fmaf(py, invH2, -1.0f);

        float rgbv[3] = {r, g, b};
        float t[3], aj[3], dj[3], hcj[3];
#pragma unroll
        for (int j = 0; j < 3; j++) {
            float4 A  = s_cpA[j * 4 + c];
            float4 Bq = s_cpB[j * 4 + c];
            float du = u - A.x;
            float dv = v - A.y;
            float r2 = fmaf(du, du, dv * dv);
            float gn = fmaf(r2, fmaf(r2, fmaf(r2, Bq.x, A.w), A.z), 1.0f);
            t[j]   = rgbv[j] * gn;
            dj[j]  = Bq.y;
            aj[j]  = Bq.z;
            hcj[j] = Bq.w;
        }

        float4 q  = s_q[f];
        uint2  uo = s_u[f];
        float2 m0102 = h22f2(__float_as_uint(q.w));
        float2 m1012 = h22f2(uo.x);
        float2 m2021 = h22f2(uo.y);

        float y0 = fmaf(q.x,     t[0], fmaf(m0102.x, t[1], m0102.y * t[2]));
        float y1 = fmaf(m1012.x, t[0], fmaf(q.y,     t[1], m1012.y * t[2]));
        float y2 = fmaf(m2021.x, t[0], fmaf(m2021.y, t[1], q.z     * t[2]));
        float yv[3] = {y0, y1, y2};

        float4 HB = s_hb[c];
        float hb[3] = {HB.x, HB.y, HB.z};
#pragma unroll
        for (int j = 0; j < 3; j++) {
            float xp  = fast_ex2(aj[j] * fast_lg2(fmaxf(yv[j], 1e-6f)));
            float arg = (xp - dj[j]) * hcj[j];
            out[3 * i + j] = fmaf(hb[j], fast_tanh(arg), hb[j]);
        }
    }
}

extern "C" void kernel_launch(void* const* d_in, const int* in_sizes, int n_in,
                              void* d_out, int out_size) {
    const float* expo   = (const float*)d_in[0];
    const float* vig    = (const float*)d_in[1];
    const float* colp   = (const float*)d_in[2];
    const float* crf    = (const float*)d_in[3];
    const float* rgb    = (const float*)d_in[4];
    const float* coords = (const float*)d_in[5];
    const int*   cam    = (const int*)d_in[6];
    const int*   frm    = (const int*)d_in[7];
    const int*   pW     = (const int*)d_in[8];
    const int*   pH     = (const int*)d_in[9];
    float* out = (float*)d_out;

    int F = in_sizes[0];
    int C = in_sizes[1] / 15;
    int B = in_sizes[6];
    if (F > MAX_F) F = MAX_F;   // table capacity guard (problem uses F=1000)

    // s_q[F] + cpA[12] + cpB[12] + hb[4] + s_u[F]
    size_t shmem = (size_t)F * 16 + 28 * 16 + (size_t)F * 8;

    {
        int pthreads = 256;
        int pwork = (F > C * 3) ? F : C * 3;
        int pblocks = (pwork + pthreads - 1) / pthreads;
        ppisp_precompute<<<pblocks, pthreads>>>(expo, vig, colp, crf, F, C);
    }

    static bool attr_done = false;
    if (!attr_done) {
        cudaFuncSetAttribute(ppisp_main,
                             cudaFuncAttributeMaxDynamicSharedMemorySize,
                             (int)shmem > 49152 ? (int)shmem : 49152);
        attr_done = true;
    }

    int blocks = (B + 255) / 256;
    int maxb = 148 * 8;
    if (blocks > maxb) blocks = maxb;
    ppisp_main<<<blocks, 256, shmem>>>(rgb, coords, cam, frm, pW, pH,
                                       out, B, F);
}

// round 10
// speedup vs baseline: 1.2359x; 1.1424x over previous
#include <cuda_runtime.h>
#include <cuda_fp16.h>

// PPISP pipeline. Round 10 = R7 (best-tied) + software-pipelined streaming
// prefetch + streaming cache hints + pre-folded -d*hc.
//  - 1 point/thread; next iteration's 7 streaming inputs prefetched into
//    registers while current iteration computes (hides ~500cyc DRAM latency).
//  - frame record 24B mixed (R7): s_q {m00,m11,m22,h2(m01,m02)} + s_u 8B
//  - camera: s_Pa[j*4+c] = {h2(v0,v1), h2(p2,p3), h2(p4,mhd), a}  (R7 packing,
//    mhd = -d*0.5/c folded), s_HC[c] = {h2(hc,hb) x3}
//  - out = hb + hb*tanh(fma(xp, hc, mhd))

#define MAX_F 4096

__device__ float4 g_q[MAX_F];
__device__ uint2  g_u[MAX_F];
__device__ __align__(128) float4 g_Pa[3 * 4];   // [j][c]
__device__ __align__(64)  float4 g_HC[4];

__device__ __forceinline__ unsigned int f2h2(float a, float b) {
    __half2 h = __floats2half2_rn(a, b);
    return *reinterpret_cast<unsigned int*>(&h);
}
__device__ __forceinline__ float2 h22f2(unsigned int u) {
    __half2 h = *reinterpret_cast<__half2*>(&u);
    return __half22float2(h);
}

__global__ void ppisp_precompute(const float* __restrict__ expo,
                                 const float* __restrict__ vig,
                                 const float* __restrict__ colp,
                                 const float* __restrict__ crf,
                                 int F, int C)
{
    int t = blockIdx.x * blockDim.x + threadIdx.x;
    if (t < F) {
        float e  = exp2f(expo[t]);
        const float* cp = colp + t * 8;
        float s0 = e * expf(cp[0]);
        float s1 = e;
        float s2 = e * expf(cp[1]);
        float o0 = cp[2], o1 = cp[3], o2 = cp[4];
        float o3 = cp[5], o4 = cp[6], o5 = cp[7];
        float m00 = (1.0f - o0 - o1) * s0, m01 = o0 * s1, m02 = o1 * s2;
        float m10 = o2 * s0, m11 = (1.0f - o2 - o3) * s1, m12 = o3 * s2;
        float m20 = o4 * s0, m21 = o5 * s1, m22 = (1.0f - o4 - o5) * s2;
        float4 q;
        q.x = m00; q.y = m11; q.z = m22;
        q.w = __uint_as_float(f2h2(m01, m02));
        g_q[t] = q;
        g_u[t] = make_uint2(f2h2(m10, m12), f2h2(m20, m21));
    }
    if (blockIdx.x == 0 && (int)threadIdx.x < C * 3 && (int)threadIdx.x < 12) {
        int c = threadIdx.x / 3;
        int j = threadIdx.x % 3;
        const float* vp = vig + c * 15 + j * 5;
        const float* kp = crf + c * 12 + j * 4;
        float a  = log1pf(expf(kp[0])) + 0.3f;   // accurate softplus (once)
        float cc = log1pf(expf(kp[2])) + 0.1f;
        float d  = kp[3];
        float hc  = 0.5f / cc;
        float mhd = -d * hc;
        float4 P;
        P.x = __uint_as_float(f2h2(vp[0], vp[1]));
        P.y = __uint_as_float(f2h2(vp[2], vp[3]));
        P.z = __uint_as_float(f2h2(vp[4], mhd));
        P.w = a;
        g_Pa[j * 4 + c] = P;
    }
    if (blockIdx.x == 0 && (int)threadIdx.x < C && (int)threadIdx.x < 4) {
        int c = threadIdx.x;
        const float* kp = crf + c * 12;
        float4 H; float* Hf = (float*)&H;
#pragma unroll
        for (int j = 0; j < 3; j++) {
            float b  = log1pf(expf(kp[4 * j + 1])) + 0.3f;
            float cc = log1pf(expf(kp[4 * j + 2])) + 0.1f;
            Hf[j] = __uint_as_float(f2h2(0.5f / cc, 0.5f * b));
        }
        Hf[3] = 0.0f;
        g_HC[c] = H;
    }
}

__device__ __forceinline__ float fast_lg2(float x) {
    float y; asm("lg2.approx.f32 %0, %1;" : "=f"(y) : "f"(x)); return y;
}
__device__ __forceinline__ float fast_ex2(float x) {
    float y; asm("ex2.approx.f32 %0, %1;" : "=f"(y) : "f"(x)); return y;
}
__device__ __forceinline__ float fast_tanh(float x) {
    float y; asm("tanh.approx.f32 %0, %1;" : "=f"(y) : "f"(x)); return y;
}

__global__ void __launch_bounds__(256, 6)
ppisp_main(const float* __restrict__ rgb,
           const float* __restrict__ coords,
           const int*   __restrict__ cam,
           const int*   __restrict__ frm,
           const int*   __restrict__ pW,
           const int*   __restrict__ pH,
           float* __restrict__ out,
           int B, int F)
{
    extern __shared__ float4 smbase[];
    float4* s_q  = smbase;                  // [F] 16B
    float4* s_Pa = s_q + F;                 // [12]
    float4* s_HC = s_Pa + 12;               // [4]
    uint2*  s_u  = (uint2*)(s_HC + 4);      // [F] 8B

    for (int i = threadIdx.x; i < F; i += blockDim.x) {
        s_q[i] = g_q[i];
        s_u[i] = g_u[i];
    }
    if (threadIdx.x < 12) s_Pa[threadIdx.x] = g_Pa[threadIdx.x];
    if (threadIdx.x < 4)  s_HC[threadIdx.x] = g_HC[threadIdx.x];
    __syncthreads();

    float invW2 = 2.0f / (float)__ldg(pW);
    float invH2 = 2.0f / (float)__ldg(pH);

    int stride = gridDim.x * blockDim.x;
    int i = blockIdx.x * blockDim.x + threadIdx.x;
    if (i >= B) return;

    // prefetch first iteration's streaming inputs
    float r  = __ldcs(rgb + 3 * i + 0);
    float g  = __ldcs(rgb + 3 * i + 1);
    float b  = __ldcs(rgb + 3 * i + 2);
    float px = __ldcs(coords + 2 * i + 0);
    float py = __ldcs(coords + 2 * i + 1);
    int   c  = __ldcs(cam + i);
    int   f  = __ldcs(frm + i);

    while (true) {
        int inext = i + stride;
        bool has_next = (inext < B);

        // issue next iteration's streaming loads (independent of the math below)
        float rn = 0.f, gn = 0.f, bn = 0.f, pxn = 0.f, pyn = 0.f;
        int cn = 0, fn = 0;
        if (has_next) {
            rn  = __ldcs(rgb + 3 * inext + 0);
            gn  = __ldcs(rgb + 3 * inext + 1);
            bn  = __ldcs(rgb + 3 * inext + 2);
            pxn = __ldcs(coords + 2 * inext + 0);
            pyn = __ldcs(coords + 2 * inext + 1);
            cn  = __ldcs(cam + inext);
            fn  = __ldcs(frm + inext);
        }

        // compute current point
        float u = fmaf(px, invW2, -1.0f);
        float v = fmaf(py, invH2, -1.0f);

        float rgbv[3] = {r, g, b};
        float t[3], aj[3], mhdj[3];
#pragma unroll
        for (int j = 0; j < 3; j++) {
            float4 P = s_Pa[j * 4 + c];
            float2 v01 = h22f2(__float_as_uint(P.x));
            float2 p23 = h22f2(__float_as_uint(P.y));
            float2 p4m = h22f2(__float_as_uint(P.z));
            float du = u - v01.x;
            float dv = v - v01.y;
            float r2 = fmaf(du, du, dv * dv);
            float gnv = fmaf(r2, fmaf(r2, fmaf(r2, p4m.x, p23.y), p23.x), 1.0f);
            t[j]    = rgbv[j] * gnv;
            aj[j]   = P.w;
            mhdj[j] = p4m.y;
        }

        float4 q  = s_q[f];
        uint2  uo = s_u[f];
        float2 m0102 = h22f2(__float_as_uint(q.w));
        float2 m1012 = h22f2(uo.x);
        float2 m2021 = h22f2(uo.y);

        float y0 = fmaf(q.x,     t[0], fmaf(m0102.x, t[1], m0102.y * t[2]));
        float y1 = fmaf(m1012.x, t[0], fmaf(q.y,     t[1], m1012.y * t[2]));
        float y2 = fmaf(m2021.x, t[0], fmaf(m2021.y, t[1], q.z     * t[2]));
        float yv[3] = {y0, y1, y2};

        float4 HC = s_HC[c];
        const float* Hf = (const float*)&HC;
#pragma unroll
        for (int j = 0; j < 3; j++) {
            float2 hcb = h22f2(__float_as_uint(Hf[j]));
            float xp  = fast_ex2(aj[j] * fast_lg2(fmaxf(yv[j], 1e-6f)));
            float arg = fmaf(xp, hcb.x, mhdj[j]);
            __stcs(out + 3 * i + j, fmaf(hcb.y, fast_tanh(arg), hcb.y));
        }

        if (!has_next) break;
        r = rn; g = gn; b = bn; px = pxn; py = pyn; c = cn; f = fn;
        i = inext;
    }
}

extern "C" void kernel_launch(void* const* d_in, const int* in_sizes, int n_in,
                              void* d_out, int out_size) {
    const float* expo   = (const float*)d_in[0];
    const float* vig    = (const float*)d_in[1];
    const float* colp   = (const float*)d_in[2];
    const float* crf    = (const float*)d_in[3];
    const float* rgb    = (const float*)d_in[4];
    const float* coords = (const float*)d_in[5];
    const int*   cam    = (const int*)d_in[6];
    const int*   frm    = (const int*)d_in[7];
    const int*   pW     = (const int*)d_in[8];
    const int*   pH     = (const int*)d_in[9];
    float* out = (float*)d_out;

    int F = in_sizes[0];
    int C = in_sizes[1] / 15;
    int B = in_sizes[6];
    if (F > MAX_F) F = MAX_F;   // table capacity guard (problem uses F=1000)

    // s_q[F] + s_Pa[12] + s_HC[4] + s_u[F]
    size_t shmem = (size_t)F * 16 + 16 * 16 + (size_t)F * 8;

    {
        int pthreads = 256;
        int pwork = (F > C * 3) ? F : C * 3;
        int pblocks = (pwork + pthreads - 1) / pthreads;
        ppisp_precompute<<<pblocks, pthreads>>>(expo, vig, colp, crf, F, C);
    }

    static bool attr_done = false;
    if (!attr_done) {
        cudaFuncSetAttribute(ppisp_main,
                             cudaFuncAttributeMaxDynamicSharedMemorySize,
                             (int)shmem > 49152 ? (int)shmem : 49152);
        attr_done = true;
    }

    int blocks = (B + 255) / 256;
    int maxb = 148 * 6;
    if (blocks > maxb) blocks = maxb;
    ppisp_main<<<blocks, 256, shmem>>>(rgb, coords, cam, frm, pW, pH,
                                       out, B, F);
}

// round 11
// speedup vs baseline: 1.2737x; 1.0306x over previous
#include <cuda_runtime.h>
#include <cuda_fp16.h>

// PPISP pipeline. Round 11 = R10 winner + distance-2 software pipeline.
//  - 1 point/thread; TWO iterations of streaming inputs in flight
//    (3 register buffer sets: current / arrived / in-flight).
//  - frame record 24B mixed: s_q {m00,m11,m22,h2(m01,m02)} + s_u 8B
//  - camera: s_Pa[j*4+c] = {h2(v0,v1), h2(p2,p3), h2(p4,mhd), a},
//    s_HC[c] = {h2(hc,hb) x3};  mhd = -d*0.5/c, hc = 0.5/c, hb = 0.5*b
//  - out = hb + hb*tanh(fma(xp, hc, mhd)),  xp = ex2(a*lg2(max(y,1e-6)))
//  launch_bounds(256,5): 51-reg cap, 40 warps/SM.

#define MAX_F 4096

__device__ float4 g_q[MAX_F];
__device__ uint2  g_u[MAX_F];
__device__ __align__(128) float4 g_Pa[3 * 4];   // [j][c]
__device__ __align__(64)  float4 g_HC[4];

__device__ __forceinline__ unsigned int f2h2(float a, float b) {
    __half2 h = __floats2half2_rn(a, b);
    return *reinterpret_cast<unsigned int*>(&h);
}
__device__ __forceinline__ float2 h22f2(unsigned int u) {
    __half2 h = *reinterpret_cast<__half2*>(&u);
    return __half22float2(h);
}

__global__ void ppisp_precompute(const float* __restrict__ expo,
                                 const float* __restrict__ vig,
                                 const float* __restrict__ colp,
                                 const float* __restrict__ crf,
                                 int F, int C)
{
    int t = blockIdx.x * blockDim.x + threadIdx.x;
    if (t < F) {
        float e  = exp2f(expo[t]);
        const float* cp = colp + t * 8;
        float s0 = e * expf(cp[0]);
        float s1 = e;
        float s2 = e * expf(cp[1]);
        float o0 = cp[2], o1 = cp[3], o2 = cp[4];
        float o3 = cp[5], o4 = cp[6], o5 = cp[7];
        float m00 = (1.0f - o0 - o1) * s0, m01 = o0 * s1, m02 = o1 * s2;
        float m10 = o2 * s0, m11 = (1.0f - o2 - o3) * s1, m12 = o3 * s2;
        float m20 = o4 * s0, m21 = o5 * s1, m22 = (1.0f - o4 - o5) * s2;
        float4 q;
        q.x = m00; q.y = m11; q.z = m22;
        q.w = __uint_as_float(f2h2(m01, m02));
        g_q[t] = q;
        g_u[t] = make_uint2(f2h2(m10, m12), f2h2(m20, m21));
    }
    if (blockIdx.x == 0 && (int)threadIdx.x < C * 3 && (int)threadIdx.x < 12) {
        int c = threadIdx.x / 3;
        int j = threadIdx.x % 3;
        const float* vp = vig + c * 15 + j * 5;
        const float* kp = crf + c * 12 + j * 4;
        float a  = log1pf(expf(kp[0])) + 0.3f;   // accurate softplus (once)
        float cc = log1pf(expf(kp[2])) + 0.1f;
        float d  = kp[3];
        float hc  = 0.5f / cc;
        float mhd = -d * hc;
        float4 P;
        P.x = __uint_as_float(f2h2(vp[0], vp[1]));
        P.y = __uint_as_float(f2h2(vp[2], vp[3]));
        P.z = __uint_as_float(f2h2(vp[4], mhd));
        P.w = a;
        g_Pa[j * 4 + c] = P;
    }
    if (blockIdx.x == 0 && (int)threadIdx.x < C && (int)threadIdx.x < 4) {
        int c = threadIdx.x;
        const float* kp = crf + c * 12;
        float4 H; float* Hf = (float*)&H;
#pragma unroll
        for (int j = 0; j < 3; j++) {
            float b  = log1pf(expf(kp[4 * j + 1])) + 0.3f;
            float cc = log1pf(expf(kp[4 * j + 2])) + 0.1f;
            Hf[j] = __uint_as_float(f2h2(0.5f / cc, 0.5f * b));
        }
        Hf[3] = 0.0f;
        g_HC[c] = H;
    }
}

__device__ __forceinline__ float fast_lg2(float x) {
    float y; asm("lg2.approx.f32 %0, %1;" : "=f"(y) : "f"(x)); return y;
}
__device__ __forceinline__ float fast_ex2(float x) {
    float y; asm("ex2.approx.f32 %0, %1;" : "=f"(y) : "f"(x)); return y;
}
__device__ __forceinline__ float fast_tanh(float x) {
    float y; asm("tanh.approx.f32 %0, %1;" : "=f"(y) : "f"(x)); return y;
}

struct PtIn {
    float r, g, b, px, py;
    int c, f;
};

__device__ __forceinline__ PtIn load_pt(const float* __restrict__ rgb,
                                        const float* __restrict__ coords,
                                        const int* __restrict__ cam,
                                        const int* __restrict__ frm,
                                        int i)
{
    PtIn p;
    p.r  = __ldcs(rgb + 3 * i + 0);
    p.g  = __ldcs(rgb + 3 * i + 1);
    p.b  = __ldcs(rgb + 3 * i + 2);
    p.px = __ldcs(coords + 2 * i + 0);
    p.py = __ldcs(coords + 2 * i + 1);
    p.c  = __ldcs(cam + i);
    p.f  = __ldcs(frm + i);
    return p;
}

__global__ void __launch_bounds__(256, 5)
ppisp_main(const float* __restrict__ rgb,
           const float* __restrict__ coords,
           const int*   __restrict__ cam,
           const int*   __restrict__ frm,
           const int*   __restrict__ pW,
           const int*   __restrict__ pH,
           float* __restrict__ out,
           int B, int F)
{
    extern __shared__ float4 smbase[];
    float4* s_q  = smbase;                  // [F] 16B
    float4* s_Pa = s_q + F;                 // [12]
    float4* s_HC = s_Pa + 12;               // [4]
    uint2*  s_u  = (uint2*)(s_HC + 4);      // [F] 8B

    for (int i = threadIdx.x; i < F; i += blockDim.x) {
        s_q[i] = g_q[i];
        s_u[i] = g_u[i];
    }
    if (threadIdx.x < 12) s_Pa[threadIdx.x] = g_Pa[threadIdx.x];
    if (threadIdx.x < 4)  s_HC[threadIdx.x] = g_HC[threadIdx.x];
    __syncthreads();

    float invW2 = 2.0f / (float)__ldg(pW);
    float invH2 = 2.0f / (float)__ldg(pH);

    int stride = gridDim.x * blockDim.x;
    int i = blockIdx.x * blockDim.x + threadIdx.x;
    if (i >= B) return;

    // distance-2 pipeline: a = current, b = arrived(i+s), c = in-flight(i+2s)
    PtIn a = load_pt(rgb, coords, cam, frm, i);
    bool hasb = (i + stride < B);
    PtIn b;
    if (hasb) b = load_pt(rgb, coords, cam, frm, i + stride);

    while (true) {
        bool hasc = (i + 2 * stride < B);
        PtIn cbuf;
        if (hasc) cbuf = load_pt(rgb, coords, cam, frm, i + 2 * stride);

        // ---- compute current point (a) ----
        {
            float u = fmaf(a.px, invW2, -1.0f);
            float v = fmaf(a.py, invH2, -1.0f);

            float rgbv[3] = {a.r, a.g, a.b};
            float t[3], aj[3], mhdj[3];
#pragma unroll
            for (int j = 0; j < 3; j++) {
                float4 P = s_Pa[j * 4 + a.c];
                float2 v01 = h22f2(__float_as_uint(P.x));
                float2 p23 = h22f2(__float_as_uint(P.y));
                float2 p4m = h22f2(__float_as_uint(P.z));
                float du = u - v01.x;
                float dv = v - v01.y;
                float r2 = fmaf(du, du, dv * dv);
                float gnv = fmaf(r2, fmaf(r2, fmaf(r2, p4m.x, p23.y), p23.x), 1.0f);
                t[j]    = rgbv[j] * gnv;
                aj[j]   = P.w;
                mhdj[j] = p4m.y;
            }

            float4 q  = s_q[a.f];
            uint2  uo = s_u[a.f];
            float2 m0102 = h22f2(__float_as_uint(q.w));
            float2 m1012 = h22f2(uo.x);
            float2 m2021 = h22f2(uo.y);

            float y0 = fmaf(q.x,     t[0], fmaf(m0102.x, t[1], m0102.y * t[2]));
            float y1 = fmaf(m1012.x, t[0], fmaf(q.y,     t[1], m1012.y * t[2]));
            float y2 = fmaf(m2021.x, t[0], fmaf(m2021.y, t[1], q.z     * t[2]));
            float yv[3] = {y0, y1, y2};

            float4 HC = s_HC[a.c];
            const float* Hf = (const float*)&HC;
#pragma unroll
            for (int j = 0; j < 3; j++) {
                float2 hcb = h22f2(__float_as_uint(Hf[j]));
                float xp  = fast_ex2(aj[j] * fast_lg2(fmaxf(yv[j], 1e-6f)));
                float arg = fmaf(xp, hcb.x, mhdj[j]);
                __stcs(out + 3 * i + j, fmaf(hcb.y, fast_tanh(arg), hcb.y));
            }
        }

        if (!hasb) break;
        a = b;
        b = cbuf;
        hasb = hasc;
        i += stride;
    }
}

extern "C" void kernel_launch(void* const* d_in, const int* in_sizes, int n_in,
                              void* d_out, int out_size) {
    const float* expo   = (const float*)d_in[0];
    const float* vig    = (const float*)d_in[1];
    const float* colp   = (const float*)d_in[2];
    const float* crf    = (const float*)d_in[3];
    const float* rgb    = (const float*)d_in[4];
    const float* coords = (const float*)d_in[5];
    const int*   cam    = (const int*)d_in[6];
    const int*   frm    = (const int*)d_in[7];
    const int*   pW     = (const int*)d_in[8];
    const int*   pH     = (const int*)d_in[9];
    float* out = (float*)d_out;

    int F = in_sizes[0];
    int C = in_sizes[1] / 15;
    int B = in_sizes[6];
    if (F > MAX_F) F = MAX_F;   // table capacity guard (problem uses F=1000)

    // s_q[F] + s_Pa[12] + s_HC[4] + s_u[F]
    size_t shmem = (size_t)F * 16 + 16 * 16 + (size_t)F * 8;

    {
        int pthreads = 256;
        int pwork = (F > C * 3) ? F : C * 3;
        int pblocks = (pwork + pthreads - 1) / pthreads;
        ppisp_precompute<<<pblocks, pthreads>>>(expo, vig, colp, crf, F, C);
    }

    static bool attr_done = false;
    if (!attr_done) {
        cudaFuncSetAttribute(ppisp_main,
                             cudaFuncAttributeMaxDynamicSharedMemorySize,
                             (int)shmem > 49152 ? (int)shmem : 49152);
        attr_done = true;
    }

    int blocks = (B + 255) / 256;
    int maxb = 148 * 5;
    if (blocks > maxb) blocks = maxb;
    ppisp_main<<<blocks, 256, shmem>>>(rgb, coords, cam, frm, pW, pH,
                                       out, B, F);
}